// round 8
// baseline (speedup 1.0000x reference)
#include <cuda_runtime.h>
#include <stdint.h>

#define NUM_BINS 256
#define NCH 48                       // B*C = 16*3
#define NCH_CHUNK 16                 // channels per pipeline chunk
#define NCHUNKS (NCH / NCH_CHUNK)    // 3
#define NPIX (1024 * 1024)           // H*W per channel
#define N4 (NPIX / 4)                // 262144 uchar4/float4 groups per channel
#define NQ (N4 / 4)                  // 65536 per quarter-stream
#define BLK_PER_CH 32
#define THREADS 256
#define CH_THREADS (BLK_PER_CH * THREADS)   // 8192
#define ITERS (N4 / CH_THREADS)             // exactly 32

// Scratch (device globals — allocation-free, zero-initialized at module load)
__device__ int           g_hist[NCH * NUM_BINS];
__device__ float         g_cdf[NCH * NUM_BINS];
__device__ int           g_count[NCH];                  // last-block counters
__device__ unsigned char g_bins[(size_t)NCH * NPIX];    // 48 MiB

__device__ __forceinline__ int quant(float v) {
    return (int)(fminf(fmaxf(v, 0.0f), 1.0f) * 255.0f); // already in [0,255]
}

// ---------------------------------------------------------------------------
// Kernel 1: histogram + bin store for one 16-channel chunk.
//   The LAST block per channel also computes the CDF (fence+counter pattern)
//   and re-zeros g_hist for the next replay.
//   grid = (BLK_PER_CH, NCH_CHUNK), block = 256
// ---------------------------------------------------------------------------
__global__ void __launch_bounds__(THREADS) hist_kernel(const float* __restrict__ x,
                                                       int cbase) {
    __shared__ int   sh[8 * NUM_BINS];          // 8 warps x 256 bins = 8 KB
    __shared__ float sscan[NUM_BINS];
    __shared__ int   s_last;
    const int c    = cbase + blockIdx.y;
    const int warp = threadIdx.x >> 5;
    int* swh = &sh[warp * NUM_BINS];

    #pragma unroll
    for (int i = threadIdx.x; i < 8 * NUM_BINS; i += THREADS) sh[i] = 0;
    __syncthreads();

    const float4* xc = reinterpret_cast<const float4*>(x + (size_t)c * NPIX);
    uchar4*       bc = reinterpret_cast<uchar4*>(g_bins + (size_t)c * NPIX);

    const int base = blockIdx.x * THREADS + threadIdx.x;
    #pragma unroll 2
    for (int k = 0; k < ITERS; k++) {
        int i = base + k * CH_THREADS;
        float4 v = xc[i];
        int q0 = quant(v.x), q1 = quant(v.y), q2 = quant(v.z), q3 = quant(v.w);

        atomicAdd(&swh[q0], 1);
        atomicAdd(&swh[q1], 1);
        atomicAdd(&swh[q2], 1);
        atomicAdd(&swh[q3], 1);

        bc[i] = make_uchar4((unsigned char)q0, (unsigned char)q1,
                            (unsigned char)q2, (unsigned char)q3);
    }
    __syncthreads();

    // flush per-warp copies to global hist
    {
        int bin = threadIdx.x;
        int sum = 0;
        #pragma unroll
        for (int w = 0; w < 8; w++) sum += sh[w * NUM_BINS + bin];
        if (sum) atomicAdd(&g_hist[c * NUM_BINS + bin], sum);
    }

    // last-block-per-channel: compute CDF in-kernel (saves a launch)
    __threadfence();
    __syncthreads();
    if (threadIdx.x == 0) {
        int v = atomicAdd(&g_count[c], 1);
        s_last = (v == BLK_PER_CH - 1);
    }
    __syncthreads();

    if (s_last) {
        const int t = threadIdx.x;
        sscan[t] = (float)__ldcg(&g_hist[c * NUM_BINS + t]);  // L2-coherent read
        __syncthreads();

        #pragma unroll
        for (int off = 1; off < NUM_BINS; off <<= 1) {
            float v = (t >= off) ? sscan[t - off] : 0.0f;
            __syncthreads();
            sscan[t] += v;
            __syncthreads();
        }

        float total = sscan[NUM_BINS - 1];
        g_cdf[c * NUM_BINS + t] = sscan[t] / fmaxf(total, 1.0f);
        g_hist[c * NUM_BINS + t] = 0;          // restore zero-invariant
        if (t == 0) g_count[c] = 0;            // reset counter for replay
    }
}

// ---------------------------------------------------------------------------
// Kernel 2: remap one 16-channel chunk — bins are L2-resident (just written).
//   Plain 1 KB LUT, 4 independent quarter-streams, streaming output stores.
//   grid = (BLK_PER_CH, NCH_CHUNK), block = 256
// ---------------------------------------------------------------------------
__global__ void __launch_bounds__(THREADS) remap_kernel(float* __restrict__ out,
                                                        int cbase) {
    __shared__ float scdf[NUM_BINS];
    const int c = cbase + blockIdx.y;

    scdf[threadIdx.x] = g_cdf[c * NUM_BINS + threadIdx.x];
    __syncthreads();

    const uchar4* bc = reinterpret_cast<const uchar4*>(g_bins + (size_t)c * NPIX);
    float4*       oc = reinterpret_cast<float4*>(out + (size_t)c * NPIX);

    const int stride = gridDim.x * blockDim.x;          // 8192
    for (int i = blockIdx.x * blockDim.x + threadIdx.x; i < NQ; i += stride) {
        uchar4 qa = __ldcs(&bc[i]);                     // dead after this read
        uchar4 qb = __ldcs(&bc[i + NQ]);
        uchar4 qc = __ldcs(&bc[i + 2 * NQ]);
        uchar4 qd = __ldcs(&bc[i + 3 * NQ]);

        float4 ra, rb, rc, rd;
        ra.x = scdf[qa.x]; ra.y = scdf[qa.y]; ra.z = scdf[qa.z]; ra.w = scdf[qa.w];
        rb.x = scdf[qb.x]; rb.y = scdf[qb.y]; rb.z = scdf[qb.z]; rb.w = scdf[qb.w];
        rc.x = scdf[qc.x]; rc.y = scdf[qc.y]; rc.z = scdf[qc.z]; rc.w = scdf[qc.w];
        rd.x = scdf[qd.x]; rd.y = scdf[qd.y]; rd.z = scdf[qd.z]; rd.w = scdf[qd.w];

        __stcs(&oc[i],          ra);
        __stcs(&oc[i + NQ],     rb);
        __stcs(&oc[i + 2 * NQ], rc);
        __stcs(&oc[i + 3 * NQ], rd);
    }
}

// ---------------------------------------------------------------------------
extern "C" void kernel_launch(void* const* d_in, const int* in_sizes, int n_in,
                              void* d_out, int out_size) {
    const float* x   = (const float*)d_in[0];
    float*       out = (float*)d_out;

    dim3 grid(BLK_PER_CH, NCH_CHUNK);       // 512 CTAs per launch
    for (int ch = 0; ch < NCHUNKS; ch++) {
        hist_kernel<<<grid, THREADS>>>(x, ch * NCH_CHUNK);
        remap_kernel<<<grid, THREADS>>>(out, ch * NCH_CHUNK);
    }
}

// round 9
// speedup vs baseline: 1.1513x; 1.1513x over previous
#include <cuda_runtime.h>
#include <stdint.h>

#define NUM_BINS 256
#define NCH 48                       // B*C = 16*3
#define NCH_CHUNK 16                 // channels per pipeline chunk
#define NCHUNKS (NCH / NCH_CHUNK)    // 3
#define NPIX (1024 * 1024)           // H*W per channel
#define N4 (NPIX / 4)                // 262144 uchar4/float4 groups per channel
#define NQ (N4 / 4)                  // 65536 per quarter-stream
#define BLK_PER_CH 64                // 64 x 16 = 1024 CTAs per launch
#define THREADS 256
#define CH_THREADS (BLK_PER_CH * THREADS)   // 16384
#define ITERS (N4 / CH_THREADS)             // exactly 16

// Scratch (device globals — allocation-free, zero-initialized at module load)
__device__ int           g_hist[NCH * NUM_BINS];
__device__ float         g_cdf[NCH * NUM_BINS];
__device__ int           g_count[NCH];                  // last-block counters
__device__ unsigned char g_bins[(size_t)NCH * NPIX];    // 48 MiB

__device__ __forceinline__ int quant(float v) {
    return (int)(fminf(fmaxf(v, 0.0f), 1.0f) * 255.0f); // already in [0,255]
}

// ---------------------------------------------------------------------------
// Kernel 1: histogram + bin store for one 16-channel chunk.
//   Plain float4 loads (the 42.5 µs shape). Last block per channel computes
//   the CDF in-kernel (fence+counter) and re-zeros g_hist for the next replay.
//   grid = (BLK_PER_CH, NCH_CHUNK), block = 256
// ---------------------------------------------------------------------------
__global__ void __launch_bounds__(THREADS) hist_kernel(const float* __restrict__ x,
                                                       int cbase) {
    __shared__ int   sh[8 * NUM_BINS];          // 8 warps x 256 bins = 8 KB
    __shared__ float sscan[NUM_BINS];
    __shared__ int   s_last;
    const int c    = cbase + blockIdx.y;
    const int warp = threadIdx.x >> 5;
    int* swh = &sh[warp * NUM_BINS];

    #pragma unroll
    for (int i = threadIdx.x; i < 8 * NUM_BINS; i += THREADS) sh[i] = 0;
    __syncthreads();

    const float4* xc = reinterpret_cast<const float4*>(x + (size_t)c * NPIX);
    uchar4*       bc = reinterpret_cast<uchar4*>(g_bins + (size_t)c * NPIX);

    const int base = blockIdx.x * THREADS + threadIdx.x;
    #pragma unroll 2
    for (int k = 0; k < ITERS; k++) {
        int i = base + k * CH_THREADS;
        float4 v = xc[i];
        int q0 = quant(v.x), q1 = quant(v.y), q2 = quant(v.z), q3 = quant(v.w);

        atomicAdd(&swh[q0], 1);
        atomicAdd(&swh[q1], 1);
        atomicAdd(&swh[q2], 1);
        atomicAdd(&swh[q3], 1);

        bc[i] = make_uchar4((unsigned char)q0, (unsigned char)q1,
                            (unsigned char)q2, (unsigned char)q3);
    }
    __syncthreads();

    // flush per-warp copies to global hist
    {
        int bin = threadIdx.x;
        int sum = 0;
        #pragma unroll
        for (int w = 0; w < 8; w++) sum += sh[w * NUM_BINS + bin];
        if (sum) atomicAdd(&g_hist[c * NUM_BINS + bin], sum);
    }

    // last-block-per-channel: compute CDF in-kernel (saves a launch)
    __threadfence();
    __syncthreads();
    if (threadIdx.x == 0) {
        int v = atomicAdd(&g_count[c], 1);
        s_last = (v == BLK_PER_CH - 1);
    }
    __syncthreads();

    if (s_last) {
        const int t = threadIdx.x;
        sscan[t] = (float)__ldcg(&g_hist[c * NUM_BINS + t]);  // L2-coherent read
        __syncthreads();

        #pragma unroll
        for (int off = 1; off < NUM_BINS; off <<= 1) {
            float v = (t >= off) ? sscan[t - off] : 0.0f;
            __syncthreads();
            sscan[t] += v;
            __syncthreads();
        }

        float total = sscan[NUM_BINS - 1];
        g_cdf[c * NUM_BINS + t] = sscan[t] / fmaxf(total, 1.0f);
        g_hist[c * NUM_BINS + t] = 0;          // restore zero-invariant
        if (t == 0) g_count[c] = 0;            // reset counter for replay
    }
}

// ---------------------------------------------------------------------------
// Kernel 2: remap one 16-channel chunk — bins are L2-resident (just written).
//   Plain 1 KB LUT, 4 independent quarter-streams, streaming in/out hints.
//   grid = (BLK_PER_CH, NCH_CHUNK), block = 256
// ---------------------------------------------------------------------------
__global__ void __launch_bounds__(THREADS) remap_kernel(float* __restrict__ out,
                                                        int cbase) {
    __shared__ float scdf[NUM_BINS];
    const int c = cbase + blockIdx.y;

    scdf[threadIdx.x] = g_cdf[c * NUM_BINS + threadIdx.x];
    __syncthreads();

    const uchar4* bc = reinterpret_cast<const uchar4*>(g_bins + (size_t)c * NPIX);
    float4*       oc = reinterpret_cast<float4*>(out + (size_t)c * NPIX);

    const int stride = gridDim.x * blockDim.x;          // 16384
    for (int i = blockIdx.x * blockDim.x + threadIdx.x; i < NQ; i += stride) {
        uchar4 qa = __ldcs(&bc[i]);                     // dead after this read
        uchar4 qb = __ldcs(&bc[i + NQ]);
        uchar4 qc = __ldcs(&bc[i + 2 * NQ]);
        uchar4 qd = __ldcs(&bc[i + 3 * NQ]);

        float4 ra, rb, rc, rd;
        ra.x = scdf[qa.x]; ra.y = scdf[qa.y]; ra.z = scdf[qa.z]; ra.w = scdf[qa.w];
        rb.x = scdf[qb.x]; rb.y = scdf[qb.y]; rb.z = scdf[qb.z]; rb.w = scdf[qb.w];
        rc.x = scdf[qc.x]; rc.y = scdf[qc.y]; rc.z = scdf[qc.z]; rc.w = scdf[qc.w];
        rd.x = scdf[qd.x]; rd.y = scdf[qd.y]; rd.z = scdf[qd.z]; rd.w = scdf[qd.w];

        __stcs(&oc[i],          ra);
        __stcs(&oc[i + NQ],     rb);
        __stcs(&oc[i + 2 * NQ], rc);
        __stcs(&oc[i + 3 * NQ], rd);
    }
}

// ---------------------------------------------------------------------------
extern "C" void kernel_launch(void* const* d_in, const int* in_sizes, int n_in,
                              void* d_out, int out_size) {
    const float* x   = (const float*)d_in[0];
    float*       out = (float*)d_out;

    dim3 grid(BLK_PER_CH, NCH_CHUNK);       // 1024 CTAs per launch
    for (int ch = 0; ch < NCHUNKS; ch++) {
        hist_kernel<<<grid, THREADS>>>(x, ch * NCH_CHUNK);
        remap_kernel<<<grid, THREADS>>>(out, ch * NCH_CHUNK);
    }
}

// round 10
// speedup vs baseline: 1.2243x; 1.0634x over previous
#include <cuda_runtime.h>
#include <stdint.h>

#define NUM_BINS 256
#define NCH 48                       // B*C = 16*3
#define NPIX (1024 * 1024)           // H*W per channel
#define N4 (NPIX / 4)                // 262144 float4/uchar4 groups per channel
#define NH (N4 / 2)                  // 131072 per half-stream (hist)
#define NQ (N4 / 4)                  // 65536 per quarter-stream (remap)
#define BLK_PER_CH 32
#define THREADS 256
#define CH_THREADS (BLK_PER_CH * THREADS)   // 8192
#define HITERS (NH / CH_THREADS)            // exactly 16

// Scratch (device globals — allocation-free, zero-initialized at module load)
__device__ int           g_hist[NCH * NUM_BINS];
__device__ float         g_cdf[NCH * NUM_BINS];
__device__ int           g_count[NCH];                  // last-block counters
__device__ unsigned char g_bins[(size_t)NCH * NPIX];    // 48 MiB

__device__ __forceinline__ int quant(float v) {
    return (int)(fminf(fmaxf(v, 0.0f), 1.0f) * 255.0f); // already in [0,255]
}

// ---------------------------------------------------------------------------
// Kernel 1: per-channel histogram + bin store + in-kernel CDF (last block).
//   x read evict-first (__ldcs) so the 192 MB stream doesn't evict the
//   freshly-written bins from L2 (keeps remap's read L2-hit — R6 finding).
//   Two independent half-streams per thread to cover the __ldcs latency.
//   grid = (BLK_PER_CH, NCH), block = 256
// ---------------------------------------------------------------------------
__global__ void __launch_bounds__(THREADS) hist_kernel(const float* __restrict__ x) {
    __shared__ int   sh[8 * NUM_BINS];          // 8 warps x 256 bins = 8 KB
    __shared__ float sscan[NUM_BINS];
    __shared__ int   s_last;
    const int c    = blockIdx.y;
    const int warp = threadIdx.x >> 5;
    int* swh = &sh[warp * NUM_BINS];

    #pragma unroll
    for (int i = threadIdx.x; i < 8 * NUM_BINS; i += THREADS) sh[i] = 0;
    __syncthreads();

    const float4* xc = reinterpret_cast<const float4*>(x + (size_t)c * NPIX);
    uchar4*       bc = reinterpret_cast<uchar4*>(g_bins + (size_t)c * NPIX);

    const int base = blockIdx.x * THREADS + threadIdx.x;
    #pragma unroll 2
    for (int k = 0; k < HITERS; k++) {
        int i = base + k * CH_THREADS;
        // two independent evict-first loads, front-batched
        float4 va = __ldcs(&xc[i]);
        float4 vb = __ldcs(&xc[i + NH]);

        int a0 = quant(va.x), a1 = quant(va.y), a2 = quant(va.z), a3 = quant(va.w);
        int b0 = quant(vb.x), b1 = quant(vb.y), b2 = quant(vb.z), b3 = quant(vb.w);

        atomicAdd(&swh[a0], 1); atomicAdd(&swh[a1], 1);
        atomicAdd(&swh[a2], 1); atomicAdd(&swh[a3], 1);
        atomicAdd(&swh[b0], 1); atomicAdd(&swh[b1], 1);
        atomicAdd(&swh[b2], 1); atomicAdd(&swh[b3], 1);

        bc[i]      = make_uchar4((unsigned char)a0, (unsigned char)a1,
                                 (unsigned char)a2, (unsigned char)a3);
        bc[i + NH] = make_uchar4((unsigned char)b0, (unsigned char)b1,
                                 (unsigned char)b2, (unsigned char)b3);
    }
    __syncthreads();

    // flush per-warp copies to global hist
    {
        int bin = threadIdx.x;
        int sum = 0;
        #pragma unroll
        for (int w = 0; w < 8; w++) sum += sh[w * NUM_BINS + bin];
        if (sum) atomicAdd(&g_hist[c * NUM_BINS + bin], sum);
    }

    // last-block-per-channel computes the CDF (saves a launch)
    __threadfence();
    __syncthreads();
    if (threadIdx.x == 0) {
        int v = atomicAdd(&g_count[c], 1);
        s_last = (v == BLK_PER_CH - 1);
    }
    __syncthreads();

    if (s_last) {
        const int t = threadIdx.x;
        sscan[t] = (float)__ldcg(&g_hist[c * NUM_BINS + t]);
        __syncthreads();

        #pragma unroll
        for (int off = 1; off < NUM_BINS; off <<= 1) {
            float v = (t >= off) ? sscan[t - off] : 0.0f;
            __syncthreads();
            sscan[t] += v;
            __syncthreads();
        }

        float total = sscan[NUM_BINS - 1];
        g_cdf[c * NUM_BINS + t] = sscan[t] / fmaxf(total, 1.0f);
        g_hist[c * NUM_BINS + t] = 0;          // restore zero-invariant
        if (t == 0) g_count[c] = 0;            // reset counter for replay
    }
}

// ---------------------------------------------------------------------------
// Kernel 2: remap — byte-identical to R6's measured ~43 µs shape.
//   Plain 1 KB LUT, 4 independent quarter-streams, streaming stores.
//   grid = (24, NCH), block = 256
// ---------------------------------------------------------------------------
__global__ void __launch_bounds__(THREADS) remap_kernel(float* __restrict__ out) {
    __shared__ float scdf[NUM_BINS];
    const int c = blockIdx.y;

    scdf[threadIdx.x] = g_cdf[c * NUM_BINS + threadIdx.x];
    __syncthreads();

    const uchar4* bc = reinterpret_cast<const uchar4*>(g_bins + (size_t)c * NPIX);
    float4*       oc = reinterpret_cast<float4*>(out + (size_t)c * NPIX);

    const int stride = gridDim.x * blockDim.x;          // 6144
    for (int i = blockIdx.x * blockDim.x + threadIdx.x; i < NQ; i += stride) {
        uchar4 qa = bc[i];
        uchar4 qb = bc[i + NQ];
        uchar4 qc = bc[i + 2 * NQ];
        uchar4 qd = bc[i + 3 * NQ];

        float4 ra, rb, rc, rd;
        ra.x = scdf[qa.x]; ra.y = scdf[qa.y]; ra.z = scdf[qa.z]; ra.w = scdf[qa.w];
        rb.x = scdf[qb.x]; rb.y = scdf[qb.y]; rb.z = scdf[qb.z]; rb.w = scdf[qb.w];
        rc.x = scdf[qc.x]; rc.y = scdf[qc.y]; rc.z = scdf[qc.z]; rc.w = scdf[qc.w];
        rd.x = scdf[qd.x]; rd.y = scdf[qd.y]; rd.z = scdf[qd.z]; rd.w = scdf[qd.w];

        __stcs(&oc[i],          ra);
        __stcs(&oc[i + NQ],     rb);
        __stcs(&oc[i + 2 * NQ], rc);
        __stcs(&oc[i + 3 * NQ], rd);
    }
}

// ---------------------------------------------------------------------------
extern "C" void kernel_launch(void* const* d_in, const int* in_sizes, int n_in,
                              void* d_out, int out_size) {
    const float* x   = (const float*)d_in[0];
    float*       out = (float*)d_out;

    dim3 gridH(BLK_PER_CH, NCH);    // 1536 CTAs
    hist_kernel<<<gridH, THREADS>>>(x);
    dim3 gridR(24, NCH);            // 1152 CTAs
    remap_kernel<<<gridR, THREADS>>>(out);
}

// round 11
// speedup vs baseline: 1.2598x; 1.0291x over previous
#include <cuda_runtime.h>
#include <stdint.h>

#define NUM_BINS 256
#define NCH 48                       // B*C = 16*3
#define NPIX (1024 * 1024)           // H*W per channel
#define N4 (NPIX / 4)                // 262144 float4/uchar4 groups per channel
#define NQ (N4 / 4)                  // 65536 per quarter-stream
#define BLK_PER_CH 32
#define THREADS 256
#define CH_THREADS (BLK_PER_CH * THREADS)   // 8192
#define QITERS (NQ / CH_THREADS)            // exactly 8

// Scratch (device globals — allocation-free, zero-initialized at module load)
__device__ int           g_hist[NCH * NUM_BINS];
__device__ float         g_cdf[NCH * NUM_BINS];
__device__ int           g_count[NCH];                  // last-block counters
__device__ unsigned char g_bins[(size_t)NCH * NPIX];    // 48 MiB

__device__ __forceinline__ int quant(float v) {
    return (int)(fminf(fmaxf(v, 0.0f), 1.0f) * 255.0f); // already in [0,255]
}

// ---------------------------------------------------------------------------
// Kernel 1: per-channel histogram + bin store + in-kernel CDF (last block).
//   x read evict-first (__ldcs): the 192 MB stream must not evict the
//   freshly-written bins from L2 (that residency is remap's speed).
//   FOUR independent quarter-streams per thread to cover the __ldcs latency.
//   grid = (BLK_PER_CH, NCH), block = 256
// ---------------------------------------------------------------------------
__global__ void __launch_bounds__(THREADS) hist_kernel(const float* __restrict__ x) {
    __shared__ int   sh[8 * NUM_BINS];          // 8 warps x 256 bins = 8 KB
    __shared__ float sscan[NUM_BINS];
    __shared__ int   s_last;
    const int c    = blockIdx.y;
    const int warp = threadIdx.x >> 5;
    int* swh = &sh[warp * NUM_BINS];

    #pragma unroll
    for (int i = threadIdx.x; i < 8 * NUM_BINS; i += THREADS) sh[i] = 0;
    __syncthreads();

    const float4* xc = reinterpret_cast<const float4*>(x + (size_t)c * NPIX);
    uchar4*       bc = reinterpret_cast<uchar4*>(g_bins + (size_t)c * NPIX);

    const int base = blockIdx.x * THREADS + threadIdx.x;
    #pragma unroll 2
    for (int k = 0; k < QITERS; k++) {
        int i = base + k * CH_THREADS;
        // four independent evict-first loads, front-batched
        float4 va = __ldcs(&xc[i]);
        float4 vb = __ldcs(&xc[i + NQ]);
        float4 vc = __ldcs(&xc[i + 2 * NQ]);
        float4 vd = __ldcs(&xc[i + 3 * NQ]);

        int a0 = quant(va.x), a1 = quant(va.y), a2 = quant(va.z), a3 = quant(va.w);
        int b0 = quant(vb.x), b1 = quant(vb.y), b2 = quant(vb.z), b3 = quant(vb.w);
        int c0 = quant(vc.x), c1 = quant(vc.y), c2 = quant(vc.z), c3 = quant(vc.w);
        int d0 = quant(vd.x), d1 = quant(vd.y), d2 = quant(vd.z), d3 = quant(vd.w);

        atomicAdd(&swh[a0], 1); atomicAdd(&swh[a1], 1);
        atomicAdd(&swh[a2], 1); atomicAdd(&swh[a3], 1);
        atomicAdd(&swh[b0], 1); atomicAdd(&swh[b1], 1);
        atomicAdd(&swh[b2], 1); atomicAdd(&swh[b3], 1);
        atomicAdd(&swh[c0], 1); atomicAdd(&swh[c1], 1);
        atomicAdd(&swh[c2], 1); atomicAdd(&swh[c3], 1);
        atomicAdd(&swh[d0], 1); atomicAdd(&swh[d1], 1);
        atomicAdd(&swh[d2], 1); atomicAdd(&swh[d3], 1);

        bc[i]          = make_uchar4((unsigned char)a0, (unsigned char)a1,
                                     (unsigned char)a2, (unsigned char)a3);
        bc[i + NQ]     = make_uchar4((unsigned char)b0, (unsigned char)b1,
                                     (unsigned char)b2, (unsigned char)b3);
        bc[i + 2 * NQ] = make_uchar4((unsigned char)c0, (unsigned char)c1,
                                     (unsigned char)c2, (unsigned char)c3);
        bc[i + 3 * NQ] = make_uchar4((unsigned char)d0, (unsigned char)d1,
                                     (unsigned char)d2, (unsigned char)d3);
    }
    __syncthreads();

    // flush per-warp copies to global hist
    {
        int bin = threadIdx.x;
        int sum = 0;
        #pragma unroll
        for (int w = 0; w < 8; w++) sum += sh[w * NUM_BINS + bin];
        if (sum) atomicAdd(&g_hist[c * NUM_BINS + bin], sum);
    }

    // last-block-per-channel computes the CDF (saves a launch)
    __threadfence();
    __syncthreads();
    if (threadIdx.x == 0) {
        int v = atomicAdd(&g_count[c], 1);
        s_last = (v == BLK_PER_CH - 1);
    }
    __syncthreads();

    if (s_last) {
        const int t = threadIdx.x;
        sscan[t] = (float)__ldcg(&g_hist[c * NUM_BINS + t]);
        __syncthreads();

        #pragma unroll
        for (int off = 1; off < NUM_BINS; off <<= 1) {
            float v = (t >= off) ? sscan[t - off] : 0.0f;
            __syncthreads();
            sscan[t] += v;
            __syncthreads();
        }

        float total = sscan[NUM_BINS - 1];
        g_cdf[c * NUM_BINS + t] = sscan[t] / fmaxf(total, 1.0f);
        g_hist[c * NUM_BINS + t] = 0;          // restore zero-invariant
        if (t == 0) g_count[c] = 0;            // reset counter for replay
    }
}

// ---------------------------------------------------------------------------
// Kernel 2: remap — 4-stream body unchanged (measured shape), but 32
//           blocks/channel for ~10 CTAs/SM (occ 69% → ~90%).
//   grid = (BLK_PER_CH, NCH), block = 256
// ---------------------------------------------------------------------------
__global__ void __launch_bounds__(THREADS) remap_kernel(float* __restrict__ out) {
    __shared__ float scdf[NUM_BINS];
    const int c = blockIdx.y;

    scdf[threadIdx.x] = g_cdf[c * NUM_BINS + threadIdx.x];
    __syncthreads();

    const uchar4* bc = reinterpret_cast<const uchar4*>(g_bins + (size_t)c * NPIX);
    float4*       oc = reinterpret_cast<float4*>(out + (size_t)c * NPIX);

    const int stride = gridDim.x * blockDim.x;          // 8192
    for (int i = blockIdx.x * blockDim.x + threadIdx.x; i < NQ; i += stride) {
        uchar4 qa = bc[i];
        uchar4 qb = bc[i + NQ];
        uchar4 qc = bc[i + 2 * NQ];
        uchar4 qd = bc[i + 3 * NQ];

        float4 ra, rb, rc, rd;
        ra.x = scdf[qa.x]; ra.y = scdf[qa.y]; ra.z = scdf[qa.z]; ra.w = scdf[qa.w];
        rb.x = scdf[qb.x]; rb.y = scdf[qb.y]; rb.z = scdf[qb.z]; rb.w = scdf[qb.w];
        rc.x = scdf[qc.x]; rc.y = scdf[qc.y]; rc.z = scdf[qc.z]; rc.w = scdf[qc.w];
        rd.x = scdf[qd.x]; rd.y = scdf[qd.y]; rd.z = scdf[qd.z]; rd.w = scdf[qd.w];

        __stcs(&oc[i],          ra);
        __stcs(&oc[i + NQ],     rb);
        __stcs(&oc[i + 2 * NQ], rc);
        __stcs(&oc[i + 3 * NQ], rd);
    }
}

// ---------------------------------------------------------------------------
extern "C" void kernel_launch(void* const* d_in, const int* in_sizes, int n_in,
                              void* d_out, int out_size) {
    const float* x   = (const float*)d_in[0];
    float*       out = (float*)d_out;

    dim3 grid(BLK_PER_CH, NCH);     // 1536 CTAs for both kernels
    hist_kernel<<<grid, THREADS>>>(x);
    remap_kernel<<<grid, THREADS>>>(out);
}

// round 12
// speedup vs baseline: 1.2607x; 1.0007x over previous
#include <cuda_runtime.h>
#include <stdint.h>

#define NUM_BINS 256
#define NCH 48                       // B*C = 16*3
#define NPIX (1024 * 1024)           // H*W per channel
#define N4 (NPIX / 4)                // 262144 float4/uchar4 groups per channel
#define NQ (N4 / 4)                  // 65536 per quarter-stream
#define HB 32                        // hist blocks per channel
#define RB 32                        // remap blocks per channel
#define THREADS 256
#define CH_THREADS (HB * THREADS)    // 8192
#define QITERS (NQ / CH_THREADS)     // exactly 8

// Scratch (device globals — allocation-free, zero-initialized at module load)
__device__ int           g_hist[NCH * NUM_BINS];
__device__ float         g_cdf[NCH * NUM_BINS];
__device__ int           g_count[NCH];     // hist last-block counters
__device__ int           g_count2[NCH];    // remap last-block counters
__device__ int           g_flag[NCH];      // cdf-ready flags
__device__ unsigned char g_bins[(size_t)NCH * NPIX];    // 48 MiB

__device__ __forceinline__ int quant(float v) {
    return (int)(fminf(fmaxf(v, 0.0f), 1.0f) * 255.0f); // already in [0,255]
}

// ---------------------------------------------------------------------------
// Fused kernel: blocks x<HB produce (hist + bins + CDF + flag release),
//               blocks x>=HB consume (spin on flag, then remap).
//   Producer channels' reads overlap consumer channels' writes chip-wide.
//   grid = (HB+RB, NCH), block = 256
// ---------------------------------------------------------------------------
__global__ void __launch_bounds__(THREADS) he_fused_kernel(const float* __restrict__ x,
                                                           float* __restrict__ out) {
    __shared__ int   sh[8 * NUM_BINS];          // hist: 8 warp-copies (8 KB)
    __shared__ float sscan[NUM_BINS];           // hist: scan buf / remap: LUT
    __shared__ int   s_last;
    const int c = blockIdx.y;

    if (blockIdx.x < HB) {
        // =================== PRODUCER: histogram + bins + CDF ===============
        const int warp = threadIdx.x >> 5;
        int* swh = &sh[warp * NUM_BINS];

        #pragma unroll
        for (int i = threadIdx.x; i < 8 * NUM_BINS; i += THREADS) sh[i] = 0;
        __syncthreads();

        const float4* xc = reinterpret_cast<const float4*>(x + (size_t)c * NPIX);
        uchar4*       bc = reinterpret_cast<uchar4*>(g_bins + (size_t)c * NPIX);

        const int base = blockIdx.x * THREADS + threadIdx.x;
        #pragma unroll 2
        for (int k = 0; k < QITERS; k++) {
            int i = base + k * CH_THREADS;
            float4 va = __ldcs(&xc[i]);
            float4 vb = __ldcs(&xc[i + NQ]);
            float4 vc = __ldcs(&xc[i + 2 * NQ]);
            float4 vd = __ldcs(&xc[i + 3 * NQ]);

            int a0 = quant(va.x), a1 = quant(va.y), a2 = quant(va.z), a3 = quant(va.w);
            int b0 = quant(vb.x), b1 = quant(vb.y), b2 = quant(vb.z), b3 = quant(vb.w);
            int c0 = quant(vc.x), c1 = quant(vc.y), c2 = quant(vc.z), c3 = quant(vc.w);
            int d0 = quant(vd.x), d1 = quant(vd.y), d2 = quant(vd.z), d3 = quant(vd.w);

            atomicAdd(&swh[a0], 1); atomicAdd(&swh[a1], 1);
            atomicAdd(&swh[a2], 1); atomicAdd(&swh[a3], 1);
            atomicAdd(&swh[b0], 1); atomicAdd(&swh[b1], 1);
            atomicAdd(&swh[b2], 1); atomicAdd(&swh[b3], 1);
            atomicAdd(&swh[c0], 1); atomicAdd(&swh[c1], 1);
            atomicAdd(&swh[c2], 1); atomicAdd(&swh[c3], 1);
            atomicAdd(&swh[d0], 1); atomicAdd(&swh[d1], 1);
            atomicAdd(&swh[d2], 1); atomicAdd(&swh[d3], 1);

            bc[i]          = make_uchar4((unsigned char)a0, (unsigned char)a1,
                                         (unsigned char)a2, (unsigned char)a3);
            bc[i + NQ]     = make_uchar4((unsigned char)b0, (unsigned char)b1,
                                         (unsigned char)b2, (unsigned char)b3);
            bc[i + 2 * NQ] = make_uchar4((unsigned char)c0, (unsigned char)c1,
                                         (unsigned char)c2, (unsigned char)c3);
            bc[i + 3 * NQ] = make_uchar4((unsigned char)d0, (unsigned char)d1,
                                         (unsigned char)d2, (unsigned char)d3);
        }
        __syncthreads();

        {   // flush per-warp copies
            int bin = threadIdx.x;
            int sum = 0;
            #pragma unroll
            for (int w = 0; w < 8; w++) sum += sh[w * NUM_BINS + bin];
            if (sum) atomicAdd(&g_hist[c * NUM_BINS + bin], sum);
        }

        __threadfence();
        __syncthreads();
        if (threadIdx.x == 0) {
            int v = atomicAdd(&g_count[c], 1);
            s_last = (v == HB - 1);
        }
        __syncthreads();

        if (s_last) {
            const int t = threadIdx.x;
            sscan[t] = (float)__ldcg(&g_hist[c * NUM_BINS + t]);
            __syncthreads();

            #pragma unroll
            for (int off = 1; off < NUM_BINS; off <<= 1) {
                float v = (t >= off) ? sscan[t - off] : 0.0f;
                __syncthreads();
                sscan[t] += v;
                __syncthreads();
            }

            float total = sscan[NUM_BINS - 1];
            g_cdf[c * NUM_BINS + t] = sscan[t] / fmaxf(total, 1.0f);
            g_hist[c * NUM_BINS + t] = 0;       // restore zero-invariant
            __threadfence();                    // release: cdf visible first
            if (t == 0) {
                g_count[c] = 0;                 // reset for next replay
                atomicExch(&g_flag[c], 1);      // publish cdf-ready
            }
        }
    } else {
        // =================== CONSUMER: spin on flag, then remap ==============
        if (threadIdx.x == 0) {
            while (atomicAdd(&g_flag[c], 0) == 0) __nanosleep(200);
            __threadfence();                    // acquire
        }
        __syncthreads();

        sscan[threadIdx.x] = g_cdf[c * NUM_BINS + threadIdx.x];
        __syncthreads();

        const uchar4* bc = reinterpret_cast<const uchar4*>(g_bins + (size_t)c * NPIX);
        float4*       oc = reinterpret_cast<float4*>(out + (size_t)c * NPIX);

        const int rbid = blockIdx.x - HB;
        const int base = rbid * THREADS + threadIdx.x;
        #pragma unroll 2
        for (int k = 0; k < QITERS; k++) {      // RB*THREADS == CH_THREADS
            int i = base + k * CH_THREADS;
            uchar4 qa = bc[i];
            uchar4 qb = bc[i + NQ];
            uchar4 qc = bc[i + 2 * NQ];
            uchar4 qd = bc[i + 3 * NQ];

            float4 ra, rb, rc, rd;
            ra.x = sscan[qa.x]; ra.y = sscan[qa.y]; ra.z = sscan[qa.z]; ra.w = sscan[qa.w];
            rb.x = sscan[qb.x]; rb.y = sscan[qb.y]; rb.z = sscan[qb.z]; rb.w = sscan[qb.w];
            rc.x = sscan[qc.x]; rc.y = sscan[qc.y]; rc.z = sscan[qc.z]; rc.w = sscan[qc.w];
            rd.x = sscan[qd.x]; rd.y = sscan[qd.y]; rd.z = sscan[qd.z]; rd.w = sscan[qd.w];

            __stcs(&oc[i],          ra);
            __stcs(&oc[i + NQ],     rb);
            __stcs(&oc[i + 2 * NQ], rc);
            __stcs(&oc[i + 3 * NQ], rd);
        }

        // last remap block per channel clears the flag for the next replay
        __syncthreads();
        if (threadIdx.x == 0) {
            int v = atomicAdd(&g_count2[c], 1);
            if (v == RB - 1) {
                g_count2[c] = 0;
                atomicExch(&g_flag[c], 0);
            }
        }
    }
}

// ---------------------------------------------------------------------------
extern "C" void kernel_launch(void* const* d_in, const int* in_sizes, int n_in,
                              void* d_out, int out_size) {
    const float* x   = (const float*)d_in[0];
    float*       out = (float*)d_out;

    dim3 grid(HB + RB, NCH);        // 3072 CTAs, producers first per channel
    he_fused_kernel<<<grid, THREADS>>>(x, out);
}

// round 13
// speedup vs baseline: 1.2840x; 1.0184x over previous
#include <cuda_runtime.h>
#include <stdint.h>

#define NUM_BINS 256
#define NCH 48                       // B*C = 16*3
#define NPIX (1024 * 1024)           // H*W per channel
#define N4 (NPIX / 4)                // 262144 float4/uchar4 groups per channel
#define NQ (N4 / 4)                  // 65536 per quarter-stream
#define SLICES 32                    // slices per channel (per phase)
#define THREADS 256
#define CH_THREADS (SLICES * THREADS)       // 8192
#define QITERS (NQ / CH_THREADS)            // exactly 8
#define LEAD 8                               // hist channels of lead-in
#define LEADT (LEAD * SLICES)                // 256 lead tasks
#define NTASKS (2 * NCH * SLICES)            // 3072
#define NCTA 1184                            // 148 SMs x 8 CTAs

// Scratch (device globals — allocation-free, zero-initialized at module load)
__device__ int           g_hist[NCH * NUM_BINS];
__device__ float         g_cdf[NCH * NUM_BINS];
__device__ int           g_count[NCH];     // hist slice counters
__device__ int           g_count2[NCH];    // remap slice counters
__device__ int           g_flag[NCH];      // cdf-ready flags
__device__ unsigned char g_bins[(size_t)NCH * NPIX];    // 48 MiB

__device__ __forceinline__ int quant(float v) {
    return (int)(fminf(fmaxf(v, 0.0f), 1.0f) * 255.0f); // already in [0,255]
}

// task t -> (kind, channel, slice); hist lead of LEAD channels, then
// alternating [hist c+LEAD | remap c] pairs, then remap tail.
__device__ __forceinline__ void decode(int t, int& kind, int& c, int& s) {
    if (t < LEADT) { kind = 0; c = t >> 5; s = t & 31; return; }
    int u = t - LEADT;
    int p = u >> 6, w = u & 63;
    if (p < NCH - LEAD) {
        if (w < 32) { kind = 0; c = LEAD + p; s = w; }
        else        { kind = 1; c = p;        s = w - 32; }
    } else {
        int idx = u - (NCH - LEAD) * 64;
        kind = 1; c = (NCH - LEAD) + (idx >> 5); s = idx & 31;
    }
}

// ---------------------------------------------------------------------------
__global__ void __launch_bounds__(THREADS) he_persistent(const float* __restrict__ x,
                                                         float* __restrict__ out) {
    __shared__ int   sh[8 * NUM_BINS];          // hist warp-copies (8 KB)
    __shared__ float sscan[NUM_BINS];           // scan buf / remap LUT
    __shared__ int   s_last;

    for (int t = blockIdx.x; t < NTASKS; t += NCTA) {
        int kind, c, s;
        decode(t, kind, c, s);
        __syncthreads();                        // smem reuse boundary

        if (kind == 0) {
            // ---------------- HIST slice (channel c, slice s) ----------------
            const int warp = threadIdx.x >> 5;
            int* swh = &sh[warp * NUM_BINS];

            #pragma unroll
            for (int i = threadIdx.x; i < 8 * NUM_BINS; i += THREADS) sh[i] = 0;
            __syncthreads();

            const float4* xc = reinterpret_cast<const float4*>(x + (size_t)c * NPIX);
            uchar4*       bc = reinterpret_cast<uchar4*>(g_bins + (size_t)c * NPIX);

            const int base = s * THREADS + threadIdx.x;
            #pragma unroll 2
            for (int k = 0; k < QITERS; k++) {
                int i = base + k * CH_THREADS;
                float4 va = xc[i];
                float4 vb = xc[i + NQ];
                float4 vc = xc[i + 2 * NQ];
                float4 vd = xc[i + 3 * NQ];

                int a0 = quant(va.x), a1 = quant(va.y), a2 = quant(va.z), a3 = quant(va.w);
                int b0 = quant(vb.x), b1 = quant(vb.y), b2 = quant(vb.z), b3 = quant(vb.w);
                int c0 = quant(vc.x), c1 = quant(vc.y), c2 = quant(vc.z), c3 = quant(vc.w);
                int d0 = quant(vd.x), d1 = quant(vd.y), d2 = quant(vd.z), d3 = quant(vd.w);

                atomicAdd(&swh[a0], 1); atomicAdd(&swh[a1], 1);
                atomicAdd(&swh[a2], 1); atomicAdd(&swh[a3], 1);
                atomicAdd(&swh[b0], 1); atomicAdd(&swh[b1], 1);
                atomicAdd(&swh[b2], 1); atomicAdd(&swh[b3], 1);
                atomicAdd(&swh[c0], 1); atomicAdd(&swh[c1], 1);
                atomicAdd(&swh[c2], 1); atomicAdd(&swh[c3], 1);
                atomicAdd(&swh[d0], 1); atomicAdd(&swh[d1], 1);
                atomicAdd(&swh[d2], 1); atomicAdd(&swh[d3], 1);

                bc[i]          = make_uchar4((unsigned char)a0, (unsigned char)a1,
                                             (unsigned char)a2, (unsigned char)a3);
                bc[i + NQ]     = make_uchar4((unsigned char)b0, (unsigned char)b1,
                                             (unsigned char)b2, (unsigned char)b3);
                bc[i + 2 * NQ] = make_uchar4((unsigned char)c0, (unsigned char)c1,
                                             (unsigned char)c2, (unsigned char)c3);
                bc[i + 3 * NQ] = make_uchar4((unsigned char)d0, (unsigned char)d1,
                                             (unsigned char)d2, (unsigned char)d3);
            }
            __syncthreads();

            {   // flush per-warp copies
                int bin = threadIdx.x;
                int sum = 0;
                #pragma unroll
                for (int w = 0; w < 8; w++) sum += sh[w * NUM_BINS + bin];
                if (sum) atomicAdd(&g_hist[c * NUM_BINS + bin], sum);
            }

            __threadfence();
            __syncthreads();
            if (threadIdx.x == 0) {
                int v = atomicAdd(&g_count[c], 1);
                s_last = (v == SLICES - 1);
            }
            __syncthreads();

            if (s_last) {
                const int tt = threadIdx.x;
                sscan[tt] = (float)__ldcg(&g_hist[c * NUM_BINS + tt]);
                __syncthreads();

                #pragma unroll
                for (int off = 1; off < NUM_BINS; off <<= 1) {
                    float v = (tt >= off) ? sscan[tt - off] : 0.0f;
                    __syncthreads();
                    sscan[tt] += v;
                    __syncthreads();
                }

                float total = sscan[NUM_BINS - 1];
                g_cdf[c * NUM_BINS + tt] = sscan[tt] / fmaxf(total, 1.0f);
                g_hist[c * NUM_BINS + tt] = 0;      // restore zero-invariant
                __threadfence();                     // release: cdf visible first
                if (tt == 0) {
                    g_count[c] = 0;                  // reset for next replay
                    atomicExch(&g_flag[c], 1);       // publish cdf-ready
                }
            }
        } else {
            // ---------------- REMAP slice (channel c, slice s) ----------------
            if (threadIdx.x == 0) {
                while (atomicAdd(&g_flag[c], 0) == 0) __nanosleep(128);
                __threadfence();                     // acquire
            }
            __syncthreads();

            sscan[threadIdx.x] = g_cdf[c * NUM_BINS + threadIdx.x];
            __syncthreads();

            const uchar4* bc = reinterpret_cast<const uchar4*>(g_bins + (size_t)c * NPIX);
            float4*       oc = reinterpret_cast<float4*>(out + (size_t)c * NPIX);

            const int base = s * THREADS + threadIdx.x;
            #pragma unroll 2
            for (int k = 0; k < QITERS; k++) {
                int i = base + k * CH_THREADS;
                uchar4 qa = bc[i];
                uchar4 qb = bc[i + NQ];
                uchar4 qc = bc[i + 2 * NQ];
                uchar4 qd = bc[i + 3 * NQ];

                float4 ra, rb, rc, rd;
                ra.x = sscan[qa.x]; ra.y = sscan[qa.y]; ra.z = sscan[qa.z]; ra.w = sscan[qa.w];
                rb.x = sscan[qb.x]; rb.y = sscan[qb.y]; rb.z = sscan[qb.z]; rb.w = sscan[qb.w];
                rc.x = sscan[qc.x]; rc.y = sscan[qc.y]; rc.z = sscan[qc.z]; rc.w = sscan[qc.w];
                rd.x = sscan[qd.x]; rd.y = sscan[qd.y]; rd.z = sscan[qd.z]; rd.w = sscan[qd.w];

                __stcs(&oc[i],          ra);
                __stcs(&oc[i + NQ],     rb);
                __stcs(&oc[i + 2 * NQ], rc);
                __stcs(&oc[i + 3 * NQ], rd);
            }

            __syncthreads();
            if (threadIdx.x == 0) {
                int v = atomicAdd(&g_count2[c], 1);
                if (v == SLICES - 1) {              // last remap slice: reset
                    g_count2[c] = 0;
                    atomicExch(&g_flag[c], 0);
                }
            }
        }
    }
}

// ---------------------------------------------------------------------------
extern "C" void kernel_launch(void* const* d_in, const int* in_sizes, int n_in,
                              void* d_out, int out_size) {
    const float* x   = (const float*)d_in[0];
    float*       out = (float*)d_out;

    he_persistent<<<NCTA, THREADS>>>(x, out);
}

// round 14
// speedup vs baseline: 1.3236x; 1.0309x over previous
#include <cuda_runtime.h>
#include <stdint.h>

#define NUM_BINS 256
#define NCH 48                       // B*C = 16*3
#define NPIX (1024 * 1024)           // H*W per channel
#define N4 (NPIX / 4)                // 262144 float4/uchar4 groups per channel
#define NQ (N4 / 4)                  // 65536 per quarter-stream
#define SLICES 64                    // slices per channel (per phase)
#define THREADS 256
#define CH_THREADS (SLICES * THREADS)       // 16384
#define QITERS (NQ / CH_THREADS)            // exactly 4
#define LEAD 12                              // hist channels of lead-in
#define LEADT (LEAD * SLICES)                // 768 lead tasks
#define NTASKS (2 * NCH * SLICES)            // 6144
#define NCTA 1184                            // 148 SMs x 8 CTAs

// Scratch (device globals — allocation-free, zero-initialized at module load)
__device__ int           g_hist[NCH * NUM_BINS];
__device__ float         g_cdf[NCH * NUM_BINS];
__device__ int           g_count[NCH];     // hist slice counters
__device__ int           g_count2[NCH];    // remap slice counters
__device__ int           g_flag[NCH];      // cdf-ready flags
__device__ unsigned char g_bins[(size_t)NCH * NPIX];    // 48 MiB

__device__ __forceinline__ int quant(float v) {
    return (int)(fminf(fmaxf(v, 0.0f), 1.0f) * 255.0f); // already in [0,255]
}

// task t -> (kind, channel, slice). Hist lead of LEAD channels, then
// alternating 64-task blocks [hist c+LEAD | remap c], then remap tail.
// Gap(hist c done -> remap c start) ~ 1473 tasks > NCTA: spin-free steady state.
__device__ __forceinline__ void decode(int t, int& kind, int& c, int& s) {
    if (t < LEADT) { kind = 0; c = t >> 6; s = t & 63; return; }
    int u = t - LEADT;
    int p = u >> 7, w = u & 127;
    if (p < NCH - LEAD) {
        if (w < SLICES) { kind = 0; c = LEAD + p; s = w; }
        else            { kind = 1; c = p;        s = w - SLICES; }
    } else {
        int idx = u - (NCH - LEAD) * 2 * SLICES;
        kind = 1; c = (NCH - LEAD) + (idx >> 6); s = idx & 63;
    }
}

// ---------------------------------------------------------------------------
__global__ void __launch_bounds__(THREADS) he_persistent(const float* __restrict__ x,
                                                         float* __restrict__ out) {
    __shared__ int   sh[8 * NUM_BINS];          // hist warp-copies (8 KB)
    __shared__ float sscan[NUM_BINS];           // scan buf / remap LUT
    __shared__ int   s_last;

    for (int t = blockIdx.x; t < NTASKS; t += NCTA) {
        int kind, c, s;
        decode(t, kind, c, s);
        __syncthreads();                        // smem reuse boundary

        if (kind == 0) {
            // ---------------- HIST slice (channel c, slice s) ----------------
            const int warp = threadIdx.x >> 5;
            int* swh = &sh[warp * NUM_BINS];

            #pragma unroll
            for (int i = threadIdx.x; i < 8 * NUM_BINS; i += THREADS) sh[i] = 0;
            __syncthreads();

            const float4* xc = reinterpret_cast<const float4*>(x + (size_t)c * NPIX);
            uchar4*       bc = reinterpret_cast<uchar4*>(g_bins + (size_t)c * NPIX);

            const int base = s * THREADS + threadIdx.x;
            #pragma unroll
            for (int k = 0; k < QITERS; k++) {
                int i = base + k * CH_THREADS;
                float4 va = xc[i];
                float4 vb = xc[i + NQ];
                float4 vc = xc[i + 2 * NQ];
                float4 vd = xc[i + 3 * NQ];

                int a0 = quant(va.x), a1 = quant(va.y), a2 = quant(va.z), a3 = quant(va.w);
                int b0 = quant(vb.x), b1 = quant(vb.y), b2 = quant(vb.z), b3 = quant(vb.w);
                int c0 = quant(vc.x), c1 = quant(vc.y), c2 = quant(vc.z), c3 = quant(vc.w);
                int d0 = quant(vd.x), d1 = quant(vd.y), d2 = quant(vd.z), d3 = quant(vd.w);

                atomicAdd(&swh[a0], 1); atomicAdd(&swh[a1], 1);
                atomicAdd(&swh[a2], 1); atomicAdd(&swh[a3], 1);
                atomicAdd(&swh[b0], 1); atomicAdd(&swh[b1], 1);
                atomicAdd(&swh[b2], 1); atomicAdd(&swh[b3], 1);
                atomicAdd(&swh[c0], 1); atomicAdd(&swh[c1], 1);
                atomicAdd(&swh[c2], 1); atomicAdd(&swh[c3], 1);
                atomicAdd(&swh[d0], 1); atomicAdd(&swh[d1], 1);
                atomicAdd(&swh[d2], 1); atomicAdd(&swh[d3], 1);

                bc[i]          = make_uchar4((unsigned char)a0, (unsigned char)a1,
                                             (unsigned char)a2, (unsigned char)a3);
                bc[i + NQ]     = make_uchar4((unsigned char)b0, (unsigned char)b1,
                                             (unsigned char)b2, (unsigned char)b3);
                bc[i + 2 * NQ] = make_uchar4((unsigned char)c0, (unsigned char)c1,
                                             (unsigned char)c2, (unsigned char)c3);
                bc[i + 3 * NQ] = make_uchar4((unsigned char)d0, (unsigned char)d1,
                                             (unsigned char)d2, (unsigned char)d3);
            }
            __syncthreads();

            {   // flush per-warp copies
                int bin = threadIdx.x;
                int sum = 0;
                #pragma unroll
                for (int w = 0; w < 8; w++) sum += sh[w * NUM_BINS + bin];
                if (sum) atomicAdd(&g_hist[c * NUM_BINS + bin], sum);
            }

            __threadfence();
            __syncthreads();
            if (threadIdx.x == 0) {
                int v = atomicAdd(&g_count[c], 1);
                s_last = (v == SLICES - 1);
            }
            __syncthreads();

            if (s_last) {
                const int tt = threadIdx.x;
                sscan[tt] = (float)__ldcg(&g_hist[c * NUM_BINS + tt]);
                __syncthreads();

                #pragma unroll
                for (int off = 1; off < NUM_BINS; off <<= 1) {
                    float v = (tt >= off) ? sscan[tt - off] : 0.0f;
                    __syncthreads();
                    sscan[tt] += v;
                    __syncthreads();
                }

                float total = sscan[NUM_BINS - 1];
                g_cdf[c * NUM_BINS + tt] = sscan[tt] / fmaxf(total, 1.0f);
                g_hist[c * NUM_BINS + tt] = 0;      // restore zero-invariant
                __threadfence();                     // release: cdf visible first
                if (tt == 0) {
                    g_count[c] = 0;                  // reset for next replay
                    atomicExch(&g_flag[c], 1);       // publish cdf-ready
                }
            }
        } else {
            // ---------------- REMAP slice (channel c, slice s) ----------------
            if (threadIdx.x == 0) {
                while (atomicAdd(&g_flag[c], 0) == 0) __nanosleep(64);
                __threadfence();                     // acquire
            }
            __syncthreads();

            sscan[threadIdx.x] = g_cdf[c * NUM_BINS + threadIdx.x];
            __syncthreads();

            const uchar4* bc = reinterpret_cast<const uchar4*>(g_bins + (size_t)c * NPIX);
            float4*       oc = reinterpret_cast<float4*>(out + (size_t)c * NPIX);

            const int base = s * THREADS + threadIdx.x;
            #pragma unroll
            for (int k = 0; k < QITERS; k++) {
                int i = base + k * CH_THREADS;
                uchar4 qa = bc[i];
                uchar4 qb = bc[i + NQ];
                uchar4 qc = bc[i + 2 * NQ];
                uchar4 qd = bc[i + 3 * NQ];

                float4 ra, rb, rc, rd;
                ra.x = sscan[qa.x]; ra.y = sscan[qa.y]; ra.z = sscan[qa.z]; ra.w = sscan[qa.w];
                rb.x = sscan[qb.x]; rb.y = sscan[qb.y]; rb.z = sscan[qb.z]; rb.w = sscan[qb.w];
                rc.x = sscan[qc.x]; rc.y = sscan[qc.y]; rc.z = sscan[qc.z]; rc.w = sscan[qc.w];
                rd.x = sscan[qd.x]; rd.y = sscan[qd.y]; rd.z = sscan[qd.z]; rd.w = sscan[qd.w];

                __stcs(&oc[i],          ra);
                __stcs(&oc[i + NQ],     rb);
                __stcs(&oc[i + 2 * NQ], rc);
                __stcs(&oc[i + 3 * NQ], rd);
            }

            __syncthreads();
            if (threadIdx.x == 0) {
                int v = atomicAdd(&g_count2[c], 1);
                if (v == SLICES - 1) {              // last remap slice: reset
                    g_count2[c] = 0;
                    atomicExch(&g_flag[c], 0);
                }
            }
        }
    }
}

// ---------------------------------------------------------------------------
extern "C" void kernel_launch(void* const* d_in, const int* in_sizes, int n_in,
                              void* d_out, int out_size) {
    const float* x   = (const float*)d_in[0];
    float*       out = (float*)d_out;

    he_persistent<<<NCTA, THREADS>>>(x, out);
}

// round 15
// speedup vs baseline: 1.3508x; 1.0205x over previous
#include <cuda_runtime.h>
#include <stdint.h>

#define NUM_BINS 256
#define NCH 48                       // B*C = 16*3
#define NPIX (1024 * 1024)           // H*W per channel
#define N4 (NPIX / 4)                // 262144 float4/uchar4 groups per channel
#define NQ (N4 / 4)                  // 65536 per quarter-stream
#define SLICES 64                    // slices per channel (per phase)
#define THREADS 256
#define CH_THREADS (SLICES * THREADS)       // 16384
#define QITERS (NQ / CH_THREADS)            // exactly 4
#define LEAD 10                              // hist channels of lead-in (min spin-free)
#define LEADT (LEAD * SLICES)                // 640 lead tasks
#define NTASKS (2 * NCH * SLICES)            // 6144
#define NCTA 1184                            // 148 SMs x 8 CTAs

// Scratch (device globals — allocation-free, zero-initialized at module load)
__device__ int           g_hist[NCH * NUM_BINS];
__device__ float         g_cdf[NCH * NUM_BINS];
__device__ int           g_count[NCH];     // hist slice counters
__device__ int           g_count2[NCH];    // remap slice counters
__device__ int           g_flag[NCH];      // cdf-ready flags
__device__ unsigned char g_bins[(size_t)NCH * NPIX];    // 48 MiB

__device__ __forceinline__ int quant(float v) {
    return (int)(fminf(fmaxf(v, 0.0f), 1.0f) * 255.0f); // already in [0,255]
}

// task t -> (kind, channel, slice). Hist lead of LEAD channels, then
// alternating 64-task blocks [hist c+LEAD | remap c], then remap tail.
// Steady-state gap(hist c done -> remap c start) = 128*LEAD+1 = 1281 > NCTA.
__device__ __forceinline__ void decode(int t, int& kind, int& c, int& s) {
    if (t < LEADT) { kind = 0; c = t >> 6; s = t & 63; return; }
    int u = t - LEADT;
    int p = u >> 7, w = u & 127;
    if (p < NCH - LEAD) {
        if (w < SLICES) { kind = 0; c = LEAD + p; s = w; }
        else            { kind = 1; c = p;        s = w - SLICES; }
    } else {
        int idx = u - (NCH - LEAD) * 2 * SLICES;
        kind = 1; c = (NCH - LEAD) + (idx >> 6); s = idx & 63;
    }
}

// ---------------------------------------------------------------------------
__global__ void __launch_bounds__(THREADS) he_persistent(const float* __restrict__ x,
                                                         float* __restrict__ out) {
    __shared__ int   sh[8 * NUM_BINS];          // hist warp-copies (8 KB)
    __shared__ float sscan[NUM_BINS];           // scan buf / remap LUT
    __shared__ int   s_last;

    for (int t = blockIdx.x; t < NTASKS; t += NCTA) {
        int kind, c, s;
        decode(t, kind, c, s);
        __syncthreads();                        // smem reuse boundary

        if (kind == 0) {
            // ---------------- HIST slice (channel c, slice s) ----------------
            const int warp = threadIdx.x >> 5;
            int* swh = &sh[warp * NUM_BINS];

            #pragma unroll
            for (int i = threadIdx.x; i < 8 * NUM_BINS; i += THREADS) sh[i] = 0;
            __syncthreads();

            const float4* xc = reinterpret_cast<const float4*>(x + (size_t)c * NPIX);
            uchar4*       bc = reinterpret_cast<uchar4*>(g_bins + (size_t)c * NPIX);

            const int base = s * THREADS + threadIdx.x;
            #pragma unroll
            for (int k = 0; k < QITERS; k++) {
                int i = base + k * CH_THREADS;
                float4 va = xc[i];
                float4 vb = xc[i + NQ];
                float4 vc = xc[i + 2 * NQ];
                float4 vd = xc[i + 3 * NQ];

                int a0 = quant(va.x), a1 = quant(va.y), a2 = quant(va.z), a3 = quant(va.w);
                int b0 = quant(vb.x), b1 = quant(vb.y), b2 = quant(vb.z), b3 = quant(vb.w);
                int c0 = quant(vc.x), c1 = quant(vc.y), c2 = quant(vc.z), c3 = quant(vc.w);
                int d0 = quant(vd.x), d1 = quant(vd.y), d2 = quant(vd.z), d3 = quant(vd.w);

                atomicAdd(&swh[a0], 1); atomicAdd(&swh[a1], 1);
                atomicAdd(&swh[a2], 1); atomicAdd(&swh[a3], 1);
                atomicAdd(&swh[b0], 1); atomicAdd(&swh[b1], 1);
                atomicAdd(&swh[b2], 1); atomicAdd(&swh[b3], 1);
                atomicAdd(&swh[c0], 1); atomicAdd(&swh[c1], 1);
                atomicAdd(&swh[c2], 1); atomicAdd(&swh[c3], 1);
                atomicAdd(&swh[d0], 1); atomicAdd(&swh[d1], 1);
                atomicAdd(&swh[d2], 1); atomicAdd(&swh[d3], 1);

                bc[i]          = make_uchar4((unsigned char)a0, (unsigned char)a1,
                                             (unsigned char)a2, (unsigned char)a3);
                bc[i + NQ]     = make_uchar4((unsigned char)b0, (unsigned char)b1,
                                             (unsigned char)b2, (unsigned char)b3);
                bc[i + 2 * NQ] = make_uchar4((unsigned char)c0, (unsigned char)c1,
                                             (unsigned char)c2, (unsigned char)c3);
                bc[i + 3 * NQ] = make_uchar4((unsigned char)d0, (unsigned char)d1,
                                             (unsigned char)d2, (unsigned char)d3);
            }
            __syncthreads();

            {   // flush per-warp copies
                int bin = threadIdx.x;
                int sum = 0;
                #pragma unroll
                for (int w = 0; w < 8; w++) sum += sh[w * NUM_BINS + bin];
                if (sum) atomicAdd(&g_hist[c * NUM_BINS + bin], sum);
            }

            __threadfence();
            __syncthreads();
            if (threadIdx.x == 0) {
                int v = atomicAdd(&g_count[c], 1);
                s_last = (v == SLICES - 1);
            }
            __syncthreads();

            if (s_last) {
                const int tt = threadIdx.x;
                sscan[tt] = (float)__ldcg(&g_hist[c * NUM_BINS + tt]);
                __syncthreads();

                #pragma unroll
                for (int off = 1; off < NUM_BINS; off <<= 1) {
                    float v = (tt >= off) ? sscan[tt - off] : 0.0f;
                    __syncthreads();
                    sscan[tt] += v;
                    __syncthreads();
                }

                float total = sscan[NUM_BINS - 1];
                g_cdf[c * NUM_BINS + tt] = sscan[tt] / fmaxf(total, 1.0f);
                g_hist[c * NUM_BINS + tt] = 0;      // restore zero-invariant
                __threadfence();                     // release: cdf visible first
                if (tt == 0) {
                    g_count[c] = 0;                  // reset for next replay
                    atomicExch(&g_flag[c], 1);       // publish cdf-ready
                }
            }
        } else {
            // ---------------- REMAP slice (channel c, slice s) ----------------
            if (threadIdx.x == 0) {
                while (atomicAdd(&g_flag[c], 0) == 0) __nanosleep(64);
                __threadfence();                     // acquire
            }
            __syncthreads();

            sscan[threadIdx.x] = g_cdf[c * NUM_BINS + threadIdx.x];
            __syncthreads();

            const uchar4* bc = reinterpret_cast<const uchar4*>(g_bins + (size_t)c * NPIX);
            float4*       oc = reinterpret_cast<float4*>(out + (size_t)c * NPIX);

            const int base = s * THREADS + threadIdx.x;
            #pragma unroll
            for (int k = 0; k < QITERS; k++) {
                int i = base + k * CH_THREADS;
                uchar4 qa = bc[i];
                uchar4 qb = bc[i + NQ];
                uchar4 qc = bc[i + 2 * NQ];
                uchar4 qd = bc[i + 3 * NQ];

                float4 ra, rb, rc, rd;
                ra.x = sscan[qa.x]; ra.y = sscan[qa.y]; ra.z = sscan[qa.z]; ra.w = sscan[qa.w];
                rb.x = sscan[qb.x]; rb.y = sscan[qb.y]; rb.z = sscan[qb.z]; rb.w = sscan[qb.w];
                rc.x = sscan[qc.x]; rc.y = sscan[qc.y]; rc.z = sscan[qc.z]; rc.w = sscan[qc.w];
                rd.x = sscan[qd.x]; rd.y = sscan[qd.y]; rd.z = sscan[qd.z]; rd.w = sscan[qd.w];

                __stcs(&oc[i],          ra);
                __stcs(&oc[i + NQ],     rb);
                __stcs(&oc[i + 2 * NQ], rc);
                __stcs(&oc[i + 3 * NQ], rd);
            }

            __syncthreads();
            if (threadIdx.x == 0) {
                int v = atomicAdd(&g_count2[c], 1);
                if (v == SLICES - 1) {              // last remap slice: reset
                    g_count2[c] = 0;
                    atomicExch(&g_flag[c], 0);
                }
            }
        }
    }
}

// ---------------------------------------------------------------------------
extern "C" void kernel_launch(void* const* d_in, const int* in_sizes, int n_in,
                              void* d_out, int out_size) {
    const float* x   = (const float*)d_in[0];
    float*       out = (float*)d_out;

    he_persistent<<<NCTA, THREADS>>>(x, out);
}